// round 3
// baseline (speedup 1.0000x reference)
#include <cuda_runtime.h>

#define NBINS 15
#define C 50

// Global accumulators: [0..14]=count, [15..29]=sum_acc, [30..44]=sum_conf
__device__ float g_bins[3 * NBINS];

__global__ void zero_bins_kernel() {
    int i = threadIdx.x;
    if (i < 3 * NBINS) g_bins[i] = 0.0f;
}

__global__ __launch_bounds__(256) void ece_main_kernel(
    const float* __restrict__ logits,
    const int* __restrict__ labels,   // JAX default x64-disabled: int64 -> int32
    int N)
{
    __shared__ float s_bins[3 * NBINS];
    int t = threadIdx.x;
    if (t < 3 * NBINS) s_bins[t] = 0.0f;
    __syncthreads();

    int row = blockIdx.x * blockDim.x + t;
    if (row < N) {
        const float2* p = reinterpret_cast<const float2*>(logits + (size_t)row * C);

        // Load full row into registers (25x float2 = 50 floats), high MLP.
        float2 v[C / 2];
        #pragma unroll
        for (int i = 0; i < C / 2; i++) v[i] = p[i];

        // Pass 1: max + argmax (strict > keeps first-index semantics).
        float mx = v[0].x;
        int am = 0;
        #pragma unroll
        for (int i = 0; i < C / 2; i++) {
            if (v[i].x > mx) { mx = v[i].x; am = 2 * i; }
            if (v[i].y > mx) { mx = v[i].y; am = 2 * i + 1; }
        }

        // Pass 2: sum of exp(x - mx). confidence = 1/sum (max softmax prob).
        float se = 0.0f;
        #pragma unroll
        for (int i = 0; i < C / 2; i++) {
            se += __expf(v[i].x - mx);
            se += __expf(v[i].y - mx);
        }
        float conf = __frcp_rn(se);

        float accv = (am == labels[row]) ? 1.0f : 0.0f;

        // bin = first i with (i+1)/15 >= conf  ==  ceil(15*conf) - 1, clamped.
        int bin = (int)ceilf(conf * (float)NBINS) - 1;
        bin = min(max(bin, 0), NBINS - 1);

        atomicAdd(&s_bins[bin], 1.0f);
        atomicAdd(&s_bins[NBINS + bin], accv);
        atomicAdd(&s_bins[2 * NBINS + bin], conf);
    }
    __syncthreads();

    if (t < 3 * NBINS) {
        float val = s_bins[t];
        if (val != 0.0f) atomicAdd(&g_bins[t], val);
    }
}

__global__ void finalize_kernel(float* __restrict__ out, int N) {
    if (threadIdx.x != 0 || blockIdx.x != 0) return;
    float invN = 1.0f / (float)N;
    float ece = 0.0f;
    for (int i = 0; i < NBINS; i++) {
        float cnt = g_bins[i];
        float sa  = g_bins[NBINS + i];
        float sc  = g_bins[2 * NBINS + i];
        float prop = cnt * invN;
        float denom = fmaxf(cnt, 1.0f);
        float gap = (sc - sa) / denom;
        bool nonempty = cnt > 0.0f;
        out[1 + i]  = nonempty ? gap * prop : 0.0f;          // bin_over_confidence
        out[16 + i] = prop;                                   // prop_in_bin
        if (nonempty) ece += fabsf(gap) * prop;
    }
    out[0] = ece;
}

extern "C" void kernel_launch(void* const* d_in, const int* in_sizes, int n_in,
                              void* d_out, int out_size)
{
    // Identify inputs by element count (logits has C=50x more elements).
    const float* logits;
    const int*   labels;
    int N;
    if (in_sizes[0] > in_sizes[1]) {
        logits = (const float*)d_in[0];
        labels = (const int*)d_in[1];
        N = in_sizes[1];
    } else {
        logits = (const float*)d_in[1];
        labels = (const int*)d_in[0];
        N = in_sizes[0];
    }
    float* out = (float*)d_out;

    zero_bins_kernel<<<1, 64>>>();
    int threads = 256;
    int blocks = (N + threads - 1) / threads;
    ece_main_kernel<<<blocks, threads>>>(logits, labels, N);
    finalize_kernel<<<1, 32>>>(out, N);
}

// round 4
// speedup vs baseline: 1.8365x; 1.8365x over previous
#include <cuda_runtime.h>

#define NBINS 15
#define C 50
#define TPB 128          // threads per block == rows per block
#define PAD 51           // row stride in smem words; 51 mod 32 = 19 -> conflict-free

// Global accumulators: [0..14]=count, [15..29]=sum_acc, [30..44]=sum_conf
// Zero-initialized at module load; finalize_kernel resets them after each use.
__device__ float g_bins[3 * NBINS];

__global__ __launch_bounds__(TPB) void ece_main_kernel(
    const float* __restrict__ logits,
    const int* __restrict__ labels,
    int N)
{
    __shared__ float s_rows[TPB * PAD];   // 128 * 51 * 4 = 26112 B
    __shared__ float s_bins[3 * NBINS];

    int t = threadIdx.x;
    if (t < 3 * NBINS) s_bins[t] = 0.0f;

    int row0  = blockIdx.x * TPB;
    int nrows = min(TPB, N - row0);

    // ---- Stage: coalesced float2 loads, de-strided into padded smem rows ----
    const float2* src = reinterpret_cast<const float2*>(logits + (size_t)row0 * C);
    int total2 = nrows * (C / 2);
    for (int g = t; g < total2; g += TPB) {
        float2 v = src[g];
        int r  = g / (C / 2);
        int c2 = g % (C / 2);
        s_rows[r * PAD + 2 * c2]     = v.x;
        s_rows[r * PAD + 2 * c2 + 1] = v.y;
    }
    __syncthreads();

    // ---- Per-row softmax stats from smem (conflict-free stride) ----
    if (t < nrows) {
        const float* my = &s_rows[t * PAD];

        float v[C];
        float mx;
        int am = 0;
        #pragma unroll
        for (int i = 0; i < C; i++) v[i] = my[i];
        mx = v[0];
        #pragma unroll
        for (int i = 1; i < C; i++) {
            if (v[i] > mx) { mx = v[i]; am = i; }   // strict > = first-index argmax
        }

        float se = 0.0f;
        #pragma unroll
        for (int i = 0; i < C; i++) se += __expf(v[i] - mx);
        float conf = 1.0f / se;                      // max softmax prob

        float accv = (am == labels[row0 + t]) ? 1.0f : 0.0f;

        // bin = first i with (i+1)/15 >= conf == ceil(15*conf)-1, clamped
        int bin = (int)ceilf(conf * (float)NBINS) - 1;
        bin = min(max(bin, 0), NBINS - 1);

        atomicAdd(&s_bins[bin], 1.0f);
        atomicAdd(&s_bins[NBINS + bin], accv);
        atomicAdd(&s_bins[2 * NBINS + bin], conf);
    }
    __syncthreads();

    if (t < 3 * NBINS) {
        float val = s_bins[t];
        if (val != 0.0f) atomicAdd(&g_bins[t], val);
    }
}

__global__ void finalize_kernel(float* __restrict__ out, int N) {
    if (threadIdx.x != 0 || blockIdx.x != 0) return;
    float invN = 1.0f / (float)N;
    float ece = 0.0f;
    for (int i = 0; i < NBINS; i++) {
        float cnt = g_bins[i];
        float sa  = g_bins[NBINS + i];
        float sc  = g_bins[2 * NBINS + i];
        float prop = cnt * invN;
        float denom = fmaxf(cnt, 1.0f);
        float gap = (sc - sa) / denom;
        bool nonempty = cnt > 0.0f;
        out[1 + i]  = nonempty ? gap * prop : 0.0f;   // bin_over_confidence
        out[16 + i] = prop;                            // prop_in_bin
        if (nonempty) ece += fabsf(gap) * prop;
        // reset for next graph replay (deterministic: every launch starts from 0)
        g_bins[i] = 0.0f;
        g_bins[NBINS + i] = 0.0f;
        g_bins[2 * NBINS + i] = 0.0f;
    }
    out[0] = ece;
}

extern "C" void kernel_launch(void* const* d_in, const int* in_sizes, int n_in,
                              void* d_out, int out_size)
{
    // Identify inputs by element count (logits has C=50x more elements).
    const float* logits;
    const int*   labels;
    int N;
    if (in_sizes[0] > in_sizes[1]) {
        logits = (const float*)d_in[0];
        labels = (const int*)d_in[1];
        N = in_sizes[1];
    } else {
        logits = (const float*)d_in[1];
        labels = (const int*)d_in[0];
        N = in_sizes[0];
    }
    float* out = (float*)d_out;

    int blocks = (N + TPB - 1) / TPB;
    ece_main_kernel<<<blocks, TPB>>>(logits, labels, N);
    finalize_kernel<<<1, 32>>>(out, N);
}

// round 5
// speedup vs baseline: 2.0478x; 1.1151x over previous
#include <cuda_runtime.h>

#define NBINS 15
#define C 50
#define TPB 128          // threads per block == rows per block
#define PAD 51           // smem row stride (words); 51 mod 32 = 19, gcd=1 -> conflict-free
#define NLD (C / 2)      // 25 float2 loads per thread for a full block

// Global accumulators: [0..14]=count, [15..29]=sum_acc, [30..44]=sum_conf
// Zero at module load; finalize_kernel resets after reading (graph-replay safe).
__device__ float g_bins[3 * NBINS];

__global__ __launch_bounds__(TPB) void ece_main_kernel(
    const float* __restrict__ logits,
    const int* __restrict__ labels,
    int N)
{
    __shared__ float s_rows[TPB * PAD];   // 26112 B
    __shared__ float s_bins[3 * NBINS];

    int t = threadIdx.x;
    if (t < 3 * NBINS) s_bins[t] = 0.0f;

    int row0  = blockIdx.x * TPB;
    int nrows = min(TPB, N - row0);

    int lbl = -1;
    if (t < nrows) lbl = labels[row0 + t];   // independent early load

    const float2* src = reinterpret_cast<const float2*>(logits + (size_t)row0 * C);

    if (nrows == TPB) {
        // Full block: compile-time trip count -> 25 front-batched LDG.64 (high MLP)
        float2 v[NLD];
        #pragma unroll
        for (int k = 0; k < NLD; k++) v[k] = src[t + k * TPB];
        #pragma unroll
        for (int k = 0; k < NLD; k++) {
            int g  = t + k * TPB;
            int r  = g / NLD;
            int c2 = g - r * NLD;
            s_rows[r * PAD + 2 * c2]     = v[k].x;
            s_rows[r * PAD + 2 * c2 + 1] = v[k].y;
        }
    } else {
        int total2 = nrows * NLD;
        for (int g = t; g < total2; g += TPB) {
            float2 v = src[g];
            int r  = g / NLD;
            int c2 = g - r * NLD;
            s_rows[r * PAD + 2 * c2]     = v.x;
            s_rows[r * PAD + 2 * c2 + 1] = v.y;
        }
    }
    __syncthreads();

    if (t < nrows) {
        const float* my = &s_rows[t * PAD];

        // Pass 1: max + argmax (strict > = first-index tie-break)
        float mx = my[0];
        int am = 0;
        #pragma unroll
        for (int i = 1; i < C; i++) {
            float x = my[i];
            if (x > mx) { mx = x; am = i; }
        }

        // Pass 2: sum of exp(x - mx); confidence = 1/sum
        float se = 0.0f;
        #pragma unroll
        for (int i = 0; i < C; i++) se += __expf(my[i] - mx);
        float conf = 1.0f / se;

        float accv = (am == lbl) ? 1.0f : 0.0f;

        // bin = first i with (i+1)/15 >= conf == ceil(15*conf)-1, clamped
        int bin = (int)ceilf(conf * (float)NBINS) - 1;
        bin = min(max(bin, 0), NBINS - 1);

        atomicAdd(&s_bins[bin], 1.0f);
        atomicAdd(&s_bins[NBINS + bin], accv);
        atomicAdd(&s_bins[2 * NBINS + bin], conf);
    }
    __syncthreads();

    if (t < 3 * NBINS) {
        float val = s_bins[t];
        if (val != 0.0f) atomicAdd(&g_bins[t], val);
    }
}

__global__ void finalize_kernel(float* __restrict__ out, int N) {
    if (threadIdx.x != 0 || blockIdx.x != 0) return;
    float invN = 1.0f / (float)N;
    float ece = 0.0f;
    for (int i = 0; i < NBINS; i++) {
        float cnt = g_bins[i];
        float sa  = g_bins[NBINS + i];
        float sc  = g_bins[2 * NBINS + i];
        float prop = cnt * invN;
        float denom = fmaxf(cnt, 1.0f);
        float gap = (sc - sa) / denom;
        bool nonempty = cnt > 0.0f;
        out[1 + i]  = nonempty ? gap * prop : 0.0f;   // bin_over_confidence
        out[16 + i] = prop;                            // prop_in_bin
        if (nonempty) ece += fabsf(gap) * prop;
        g_bins[i] = 0.0f;                              // reset for next replay
        g_bins[NBINS + i] = 0.0f;
        g_bins[2 * NBINS + i] = 0.0f;
    }
    out[0] = ece;
}

extern "C" void kernel_launch(void* const* d_in, const int* in_sizes, int n_in,
                              void* d_out, int out_size)
{
    const float* logits;
    const int*   labels;
    int N;
    if (in_sizes[0] > in_sizes[1]) {
        logits = (const float*)d_in[0];
        labels = (const int*)d_in[1];
        N = in_sizes[1];
    } else {
        logits = (const float*)d_in[1];
        labels = (const int*)d_in[0];
        N = in_sizes[0];
    }
    float* out = (float*)d_out;

    int blocks = (N + TPB - 1) / TPB;
    ece_main_kernel<<<blocks, TPB>>>(logits, labels, N);
    finalize_kernel<<<1, 32>>>(out, N);
}